// round 1
// baseline (speedup 1.0000x reference)
#include <cuda_runtime.h>

// Problem constants (fixed shapes for this problem instance)
#define NN     100000
#define NE     3200000
#define INDIM  512
#define HID    16
#define OUTD   64

// ---------------- device scratch (static, no allocation) ----------------
__device__ __align__(16) int   g_src[NE];
__device__ __align__(16) int   g_dst[NE];
__device__ __align__(16) int   g_srcs[NE];          // src sorted by dst (CSR adjacency)
__device__ __align__(16) int   g_deg[NN];
__device__ __align__(16) float g_dinv[NN];
__device__ __align__(16) int   g_rowptr[NN + 1];
__device__ __align__(16) int   g_cursor[NN];
__device__ __align__(16) int   g_part[256];
__device__ int g_is64;
__device__ __align__(16) float g_hn1[NN * HID];     // (X@W1) * dinv[row]
__device__ __align__(16) float g_out1[NN * HID];    // layer-1 pre-relu output (incl b1)
__device__ __align__(16) float g_hn2[NN * HID];     // relu(out1) * dinv[row]
__device__ __align__(16) float g_agg2[NN * HID];    // layer-2 aggregated (pre-projection)

// ---------------- dtype detection: int64 vs int32 edge list ----------------
__global__ void k_detect(const unsigned int* __restrict__ w) {
    if (blockIdx.x == 0 && threadIdx.x == 0) {
        int is64 = 1;
        // if int64 little-endian with values < 2^31, every odd 32-bit word is 0
        for (int i = 1; i < 64; i += 2) {
            if (w[i] != 0u) { is64 = 0; break; }
        }
        g_is64 = is64;
    }
}

__global__ void k_deg_init(int n) {
    int i = blockIdx.x * blockDim.x + threadIdx.x;
    if (i < n) g_deg[i] = 1;   // self-loop
}

__global__ void k_edge_prep(const void* __restrict__ E, int ne) {
    int e = blockIdx.x * blockDim.x + threadIdx.x;
    if (e >= ne) return;
    int s, d;
    if (g_is64) {
        const long long* e64 = (const long long*)E;
        s = (int)e64[e];
        d = (int)e64[ne + e];
    } else {
        const int* e32 = (const int*)E;
        s = e32[e];
        d = e32[ne + e];
    }
    g_src[e] = s;
    g_dst[e] = d;
    atomicAdd(&g_deg[d], 1);
}

__global__ void k_dinv(int n) {
    int i = blockIdx.x * blockDim.x + threadIdx.x;
    if (i < n) g_dinv[i] = rsqrtf((float)g_deg[i]);
}

// ---------------- exclusive scan of (deg-1) -> rowptr ----------------
__global__ void k_scan1(int n) {
    __shared__ int ss[256];
    int t = threadIdx.x;
    int base = blockIdx.x * 1024 + t * 4;
    int v[4]; int s = 0;
#pragma unroll
    for (int m = 0; m < 4; m++) {
        int idx = base + m;
        v[m] = (idx < n) ? (g_deg[idx] - 1) : 0;
        s += v[m];
    }
    ss[t] = s;
    __syncthreads();
#pragma unroll
    for (int off = 1; off < 256; off <<= 1) {
        int tv = 0;
        if (t >= off) tv = ss[t - off];
        __syncthreads();
        ss[t] += tv;
        __syncthreads();
    }
    int run = ss[t] - s;   // exclusive within block
#pragma unroll
    for (int m = 0; m < 4; m++) {
        int idx = base + m;
        if (idx < n) g_rowptr[idx] = run;
        run += v[m];
    }
    if (t == 255) g_part[blockIdx.x] = ss[255];
}

__global__ void k_scan2(int nblk, int n) {
    if (blockIdx.x == 0 && threadIdx.x == 0) {
        int run = 0;
        for (int b = 0; b < nblk; b++) {
            int tv = g_part[b];
            g_part[b] = run;
            run += tv;
        }
        g_rowptr[n] = run;
    }
}

__global__ void k_scan3(int n) {
    int i = blockIdx.x * blockDim.x + threadIdx.x;
    if (i < n) {
        int v = g_rowptr[i] + g_part[i >> 10];
        g_rowptr[i] = v;
        g_cursor[i] = v;
    }
}

// ---------------- counting-sort scatter: group edges by dst ----------------
__global__ void k_csr(int ne) {
    int e = blockIdx.x * blockDim.x + threadIdx.x;
    if (e >= ne) return;
    int d = g_dst[e];
    int pos = atomicAdd(&g_cursor[d], 1);
    g_srcs[pos] = g_src[e];
}

// ---------------- GEMM1: hn1 = (X @ W1) * dinv[row] ----------------
// block: 128 threads, tile 128 rows x 16 cols; thread: 4 rows x 4 cols
#define G1_TR 128
#define G1_KT 16
#define XSTR  20    // KT + 4 pad words: stride % 32 == 20 -> conflict-free row access
#define WSTR  516   // 512 + 4 pad words

__global__ __launch_bounds__(128) void k_gemm1(const float* __restrict__ X,
                                               const float* __restrict__ W1, int n) {
    __shared__ __align__(16) float sW[HID * WSTR];
    __shared__ __align__(16) float sX[G1_TR * XSTR];
    int t  = threadIdx.x;
    int cg = t & 3;        // column group (4 cols)
    int rg = t >> 2;       // 0..31; thread rows = rg + 32*i

    // load W1 transposed: sW[j][k]
    for (int m = t; m < INDIM * HID; m += 128) {
        int k = m >> 4, j = m & 15;
        sW[j * WSTR + k] = W1[m];
    }

    float acc[4][4];
#pragma unroll
    for (int i = 0; i < 4; i++)
#pragma unroll
        for (int j = 0; j < 4; j++) acc[i][j] = 0.f;

    int row0 = blockIdx.x * G1_TR;
    const float4* X4 = (const float4*)X;

    for (int kt = 0; kt < INDIM / G1_KT; kt++) {
        __syncthreads();
        // stage X tile: 128 rows x 16 floats
        {
            int c4 = t & 3, rl = t >> 2;
#pragma unroll
            for (int mm = 0; mm < 4; mm++) {
                int r = rl + 32 * mm;
                int grow = row0 + r;
                float4 v = make_float4(0.f, 0.f, 0.f, 0.f);
                if (grow < n) v = X4[grow * (INDIM / 4) + kt * (G1_KT / 4) + c4];
                *(float4*)&sX[r * XSTR + c4 * 4] = v;
            }
        }
        __syncthreads();
#pragma unroll
        for (int kk = 0; kk < 4; kk++) {
            float4 wv[4], xv[4];
#pragma unroll
            for (int j = 0; j < 4; j++)
                wv[j] = *(const float4*)&sW[(cg * 4 + j) * WSTR + kt * G1_KT + kk * 4];
#pragma unroll
            for (int i = 0; i < 4; i++)
                xv[i] = *(const float4*)&sX[(rg + 32 * i) * XSTR + kk * 4];
#pragma unroll
            for (int i = 0; i < 4; i++)
#pragma unroll
                for (int j = 0; j < 4; j++)
                    acc[i][j] += xv[i].x * wv[j].x + xv[i].y * wv[j].y
                               + xv[i].z * wv[j].z + xv[i].w * wv[j].w;
        }
    }

#pragma unroll
    for (int i = 0; i < 4; i++) {
        int row = row0 + rg + 32 * i;
        if (row < n) {
            float dv = g_dinv[row];
            float4 o = make_float4(acc[i][0] * dv, acc[i][1] * dv,
                                   acc[i][2] * dv, acc[i][3] * dv);
            *(float4*)&g_hn1[row * HID + cg * 4] = o;
        }
    }
}

// ---------------- gather aggregation (one warp per node) ----------------
// out[d] = dinv[d] * (sum_{e:dst=d} hn[src_e] + hn[d])  [+ bias]
__global__ void k_gather(const float* __restrict__ bias, int n, int layer) {
    int gt   = blockIdx.x * blockDim.x + threadIdx.x;
    int node = gt >> 5;
    if (node >= n) return;
    int lane = threadIdx.x & 31;
    int comp = lane & 3;   // which float4 of the 16-float row
    int sub  = lane >> 2;  // 8 parallel edge slots

    const float4* hn4 = (layer == 1) ? (const float4*)g_hn1 : (const float4*)g_hn2;
    float* out        = (layer == 1) ? g_out1 : g_agg2;

    int start = g_rowptr[node];
    int end   = g_rowptr[node + 1];

    float4 acc = make_float4(0.f, 0.f, 0.f, 0.f);
    for (int p = start + sub; p < end; p += 8) {
        int s = g_srcs[p];
        float4 v = hn4[s * 4 + comp];
        acc.x += v.x; acc.y += v.y; acc.z += v.z; acc.w += v.w;
    }
#pragma unroll
    for (int off = 4; off < 32; off <<= 1) {
        acc.x += __shfl_xor_sync(0xffffffffu, acc.x, off);
        acc.y += __shfl_xor_sync(0xffffffffu, acc.y, off);
        acc.z += __shfl_xor_sync(0xffffffffu, acc.z, off);
        acc.w += __shfl_xor_sync(0xffffffffu, acc.w, off);
    }
    if (sub == 0) {
        float4 self = hn4[node * 4 + comp];
        float dv = g_dinv[node];
        float4 o;
        o.x = (acc.x + self.x) * dv;
        o.y = (acc.y + self.y) * dv;
        o.z = (acc.z + self.z) * dv;
        o.w = (acc.w + self.w) * dv;
        if (layer == 1) {
            float4 b = ((const float4*)bias)[comp];
            o.x += b.x; o.y += b.y; o.z += b.z; o.w += b.w;
        }
        ((float4*)out)[node * 4 + comp] = o;
    }
}

// ---------------- hn2 = relu(out1) * dinv[row] ----------------
__global__ void k_hn2(int n) {
    int i = blockIdx.x * blockDim.x + threadIdx.x;   // one float4 per thread
    if (i >= n * 4) return;
    int row = i >> 2;
    float4 v = ((const float4*)g_out1)[i];
    float dv = g_dinv[row];
    float4 o = make_float4(fmaxf(v.x, 0.f) * dv, fmaxf(v.y, 0.f) * dv,
                           fmaxf(v.z, 0.f) * dv, fmaxf(v.w, 0.f) * dv);
    ((float4*)g_hn2)[i] = o;
}

// ---------------- GEMM2: out = agg2 @ W2 + b2 ----------------
// block 256: 16 rows x 16 col-groups (4 cols each). W2 column slice kept in regs.
__global__ __launch_bounds__(256) void k_gemm2(const float* __restrict__ W2,
                                               const float* __restrict__ b2,
                                               float* __restrict__ out, int n) {
    __shared__ __align__(16) float sA[16 * 17];
    int t  = threadIdx.x;
    int j4 = t & 15;
    int rl = t >> 4;

    float4 wreg[16];
    const float4* W2_4 = (const float4*)W2;
#pragma unroll
    for (int k = 0; k < 16; k++) wreg[k] = W2_4[k * 16 + j4];
    float4 bv = ((const float4*)b2)[j4];

    int row0 = blockIdx.x * 16;
    {
        int r = t >> 4, k = t & 15;
        int grow = row0 + r;
        float v = 0.f;
        if (grow < n) v = g_agg2[grow * 16 + k];
        sA[r * 17 + k] = v;
    }
    __syncthreads();

    float4 acc = bv;
#pragma unroll
    for (int k = 0; k < 16; k++) {
        float a = sA[rl * 17 + k];
        acc.x += a * wreg[k].x;
        acc.y += a * wreg[k].y;
        acc.z += a * wreg[k].z;
        acc.w += a * wreg[k].w;
    }
    int row = row0 + rl;
    if (row < n) ((float4*)out)[row * 16 + j4] = acc;
}

// ---------------- launch ----------------
extern "C" void kernel_launch(void* const* d_in, const int* in_sizes, int n_in,
                              void* d_out, int out_size) {
    const void*  E  = d_in[1];
    const float* X  = (const float*)d_in[2];
    const float* W1 = (const float*)d_in[3];
    const float* b1 = (const float*)d_in[4];
    const float* W2 = (const float*)d_in[5];
    const float* b2 = (const float*)d_in[6];
    float* out = (float*)d_out;

    int n  = in_sizes[0];
    int ne = in_sizes[1] / 2;

    k_detect<<<1, 32>>>((const unsigned int*)E);
    k_deg_init<<<(n + 255) / 256, 256>>>(n);
    k_edge_prep<<<(ne + 255) / 256, 256>>>(E, ne);
    k_dinv<<<(n + 255) / 256, 256>>>(n);

    int nblk = (n + 1023) / 1024;
    k_scan1<<<nblk, 256>>>(n);
    k_scan2<<<1, 32>>>(nblk, n);
    k_scan3<<<(n + 255) / 256, 256>>>(n);
    k_csr<<<(ne + 255) / 256, 256>>>(ne);

    k_gemm1<<<(n + G1_TR - 1) / G1_TR, 128>>>(X, W1, n);

    long long gth = (long long)n * 32;
    k_gather<<<(unsigned)((gth + 255) / 256), 256>>>(b1, n, 1);

    k_hn2<<<(n * 4 + 255) / 256, 256>>>(n);

    k_gather<<<(unsigned)((gth + 255) / 256), 256>>>(b2, n, 2);

    k_gemm2<<<(n + 15) / 16, 256>>>(W2, b2, out, n);
}

// round 2
// speedup vs baseline: 1.0158x; 1.0158x over previous
#include <cuda_runtime.h>

// Problem constants (fixed shapes for this problem instance)
#define NN     100000
#define NE     3200000
#define INDIM  512
#define HID    16
#define OUTD   64

// ---------------- device scratch (static, no allocation) ----------------
__device__ __align__(16) int2  g_edge[NE];          // packed (src,dst)
__device__ __align__(16) int   g_srcs[NE];          // src sorted by dst (CSR adjacency)
__device__ __align__(16) int   g_deg[NN];
__device__ __align__(16) float g_dinv[NN];
__device__ __align__(16) int   g_rowptr[NN + 1];
__device__ __align__(16) int   g_cursor[NN];
__device__ __align__(16) int   g_part[128];
__device__ int g_is64;
__device__ __align__(16) float g_hn1[NN * HID];     // (X@W1) * dinv[row]
__device__ __align__(16) float g_hn2[NN * HID];     // relu(layer1 out) * dinv[row]

// ---------------- init: deg=1 (self loop) + dtype detect ----------------
__global__ void k_init(const unsigned int* __restrict__ Ew, int n) {
    int i = blockIdx.x * blockDim.x + threadIdx.x;
    if (i < n) g_deg[i] = 1;
    if (blockIdx.x == 0 && threadIdx.x < 32) {
        // int64 little-endian with values < 2^31 -> every odd 32-bit word is 0
        unsigned v = Ew[2 * threadIdx.x + 1];
        unsigned any = __ballot_sync(0xffffffffu, v != 0u);
        if (threadIdx.x == 0) g_is64 = (any == 0u);
    }
}

__global__ void k_edge_prep(const void* __restrict__ E, int ne) {
    int e = blockIdx.x * blockDim.x + threadIdx.x;
    if (e >= ne) return;
    int s, d;
    if (g_is64) {
        const long long* e64 = (const long long*)E;
        s = (int)e64[e];
        d = (int)e64[ne + e];
    } else {
        const int* e32 = (const int*)E;
        s = e32[e];
        d = e32[ne + e];
    }
    g_edge[e] = make_int2(s, d);
    atomicAdd(&g_deg[d], 1);
}

// ---------------- exclusive scan of (deg-1) -> rowptr; fused dinv ----------------
__global__ void k_scan1(int n) {
    __shared__ int ss[256];
    int t = threadIdx.x;
    int base = blockIdx.x * 1024 + t * 4;
    int v[4]; int s = 0;
#pragma unroll
    for (int m = 0; m < 4; m++) {
        int idx = base + m;
        int dg = (idx < n) ? g_deg[idx] : 1;
        if (idx < n) g_dinv[idx] = rsqrtf((float)dg);
        v[m] = (idx < n) ? (dg - 1) : 0;
        s += v[m];
    }
    ss[t] = s;
    __syncthreads();
#pragma unroll
    for (int off = 1; off < 256; off <<= 1) {
        int tv = 0;
        if (t >= off) tv = ss[t - off];
        __syncthreads();
        ss[t] += tv;
        __syncthreads();
    }
    int run = ss[t] - s;   // exclusive within block
#pragma unroll
    for (int m = 0; m < 4; m++) {
        int idx = base + m;
        if (idx < n) g_rowptr[idx] = run;
        run += v[m];
    }
    if (t == 255) g_part[blockIdx.x] = ss[255];
}

// parallel scan of block partials (nblk <= 128)
__global__ void k_scan2(int nblk, int n) {
    __shared__ int ss[128];
    int t = threadIdx.x;
    int v = (t < nblk) ? g_part[t] : 0;
    ss[t] = v;
    __syncthreads();
#pragma unroll
    for (int off = 1; off < 128; off <<= 1) {
        int tv = 0;
        if (t >= off) tv = ss[t - off];
        __syncthreads();
        ss[t] += tv;
        __syncthreads();
    }
    if (t < nblk) g_part[t] = ss[t] - v;   // exclusive
    if (t == 127) g_rowptr[n] = ss[127];   // total edge count
}

__global__ void k_scan3(int n) {
    int i = blockIdx.x * blockDim.x + threadIdx.x;
    if (i < n) {
        int v = g_rowptr[i] + g_part[i >> 10];
        g_rowptr[i] = v;
        g_cursor[i] = v;
    }
}

// ---------------- counting-sort scatter: group edges by dst ----------------
__global__ void k_csr(int ne) {
    int e = blockIdx.x * blockDim.x + threadIdx.x;
    if (e >= ne) return;
    int2 sd = g_edge[e];
    int pos = atomicAdd(&g_cursor[sd.y], 1);
    g_srcs[pos] = sd.x;
}

// ---------------- GEMM1: hn1 = (X @ W1) * dinv[row] ----------------
// block: 128 threads, tile 128 rows x 16 cols; thread: 4 rows x 4 cols
#define G1_TR 128
#define G1_KT 16
#define XSTR  20    // KT + 4 pad words -> conflict-free
#define WSTR  516   // 512 + 4 pad words

__global__ __launch_bounds__(128) void k_gemm1(const float* __restrict__ X,
                                               const float* __restrict__ W1, int n) {
    __shared__ __align__(16) float sW[HID * WSTR];
    __shared__ __align__(16) float sX[G1_TR * XSTR];
    int t  = threadIdx.x;
    int cg = t & 3;        // column group (4 cols)
    int rg = t >> 2;       // 0..31; thread rows = rg + 32*i

    // load W1 transposed: sW[j][k]
    for (int m = t; m < INDIM * HID; m += 128) {
        int k = m >> 4, j = m & 15;
        sW[j * WSTR + k] = W1[m];
    }

    float acc[4][4];
#pragma unroll
    for (int i = 0; i < 4; i++)
#pragma unroll
        for (int j = 0; j < 4; j++) acc[i][j] = 0.f;

    int row0 = blockIdx.x * G1_TR;
    const float4* X4 = (const float4*)X;

    for (int kt = 0; kt < INDIM / G1_KT; kt++) {
        __syncthreads();
        {
            int c4 = t & 3, rl = t >> 2;
#pragma unroll
            for (int mm = 0; mm < 4; mm++) {
                int r = rl + 32 * mm;
                int grow = row0 + r;
                float4 v = make_float4(0.f, 0.f, 0.f, 0.f);
                if (grow < n) v = X4[grow * (INDIM / 4) + kt * (G1_KT / 4) + c4];
                *(float4*)&sX[r * XSTR + c4 * 4] = v;
            }
        }
        __syncthreads();
#pragma unroll
        for (int kk = 0; kk < 4; kk++) {
            float4 wv[4], xv[4];
#pragma unroll
            for (int j = 0; j < 4; j++)
                wv[j] = *(const float4*)&sW[(cg * 4 + j) * WSTR + kt * G1_KT + kk * 4];
#pragma unroll
            for (int i = 0; i < 4; i++)
                xv[i] = *(const float4*)&sX[(rg + 32 * i) * XSTR + kk * 4];
#pragma unroll
            for (int i = 0; i < 4; i++)
#pragma unroll
                for (int j = 0; j < 4; j++)
                    acc[i][j] += xv[i].x * wv[j].x + xv[i].y * wv[j].y
                               + xv[i].z * wv[j].z + xv[i].w * wv[j].w;
        }
    }

#pragma unroll
    for (int i = 0; i < 4; i++) {
        int row = row0 + rg + 32 * i;
        if (row < n) {
            float dv = g_dinv[row];
            float4 o = make_float4(acc[i][0] * dv, acc[i][1] * dv,
                                   acc[i][2] * dv, acc[i][3] * dv);
            *(float4*)&g_hn1[row * HID + cg * 4] = o;
        }
    }
}

// ---------------- gather layer 1 + relu + dinv-prescale (writes hn2) ----------
// hn2[d] = relu( dinv[d]*(sum hn1[src] + hn1[d]) + b1 ) * dinv[d]
__global__ __launch_bounds__(256) void k_gather_h(const float* __restrict__ b1, int n) {
    int gt   = blockIdx.x * blockDim.x + threadIdx.x;
    int node = gt >> 5;
    if (node >= n) return;
    int lane = threadIdx.x & 31;
    int comp = lane & 3;   // which float4 of the 16-float row
    int sub  = lane >> 2;  // 8 parallel edge slots

    const float4* hn4 = (const float4*)g_hn1;
    int start = g_rowptr[node];
    int end   = g_rowptr[node + 1];

    float4 acc = make_float4(0.f, 0.f, 0.f, 0.f);
    for (int p = start + sub; p < end; p += 8) {
        int s = g_srcs[p];
        float4 v = hn4[s * 4 + comp];
        acc.x += v.x; acc.y += v.y; acc.z += v.z; acc.w += v.w;
    }
    if (sub == 0) {                       // fold in self loop once
        float4 self = hn4[node * 4 + comp];
        acc.x += self.x; acc.y += self.y; acc.z += self.z; acc.w += self.w;
    }
#pragma unroll
    for (int off = 4; off < 32; off <<= 1) {
        acc.x += __shfl_xor_sync(0xffffffffu, acc.x, off);
        acc.y += __shfl_xor_sync(0xffffffffu, acc.y, off);
        acc.z += __shfl_xor_sync(0xffffffffu, acc.z, off);
        acc.w += __shfl_xor_sync(0xffffffffu, acc.w, off);
    }
    if (sub == 0) {
        float dv = g_dinv[node];
        float4 b = ((const float4*)b1)[comp];
        float4 o;
        o.x = fmaxf(acc.x * dv + b.x, 0.f) * dv;
        o.y = fmaxf(acc.y * dv + b.y, 0.f) * dv;
        o.z = fmaxf(acc.z * dv + b.z, 0.f) * dv;
        o.w = fmaxf(acc.w * dv + b.w, 0.f) * dv;
        ((float4*)g_hn2)[node * 4 + comp] = o;
    }
}

// ---------------- gather layer 2 fused with GEMM2 (writes final output) -------
// agg[d] = dinv[d]*(sum hn2[src] + hn2[d]);  out[d] = agg[d] @ W2 + b2
__global__ __launch_bounds__(256) void k_gather_out(const float* __restrict__ W2,
                                                    const float* __restrict__ b2,
                                                    float* __restrict__ out, int n) {
    __shared__ __align__(16) float sW2[HID * OUTD];
    __shared__ float sB2[OUTD];
    int t = threadIdx.x;
    for (int m = t; m < HID * OUTD; m += 256) sW2[m] = W2[m];
    if (t < OUTD) sB2[t] = b2[t];
    __syncthreads();

    int node = (blockIdx.x * 256 + t) >> 5;
    if (node >= n) return;
    int lane = t & 31;
    int comp = lane & 3;
    int sub  = lane >> 2;

    const float4* hn4 = (const float4*)g_hn2;
    int start = g_rowptr[node];
    int end   = g_rowptr[node + 1];

    float4 acc = make_float4(0.f, 0.f, 0.f, 0.f);
    for (int p = start + sub; p < end; p += 8) {
        int s = g_srcs[p];
        float4 v = hn4[s * 4 + comp];
        acc.x += v.x; acc.y += v.y; acc.z += v.z; acc.w += v.w;
    }
    if (sub == 0) {
        float4 self = hn4[node * 4 + comp];
        acc.x += self.x; acc.y += self.y; acc.z += self.z; acc.w += self.w;
    }
#pragma unroll
    for (int off = 4; off < 32; off <<= 1) {
        acc.x += __shfl_xor_sync(0xffffffffu, acc.x, off);
        acc.y += __shfl_xor_sync(0xffffffffu, acc.y, off);
        acc.z += __shfl_xor_sync(0xffffffffu, acc.z, off);
        acc.w += __shfl_xor_sync(0xffffffffu, acc.w, off);
    }
    float dv = g_dinv[node];
    acc.x *= dv; acc.y *= dv; acc.z *= dv; acc.w *= dv;

    // broadcast the 16 aggregated values to all lanes (lanes 0..3 hold comps 0..3)
    float a[HID];
#pragma unroll
    for (int c = 0; c < 4; c++) {
        a[4 * c + 0] = __shfl_sync(0xffffffffu, acc.x, c);
        a[4 * c + 1] = __shfl_sync(0xffffffffu, acc.y, c);
        a[4 * c + 2] = __shfl_sync(0xffffffffu, acc.z, c);
        a[4 * c + 3] = __shfl_sync(0xffffffffu, acc.w, c);
    }

    // each lane computes output columns lane and lane+32
    float o0 = sB2[lane];
    float o1 = sB2[lane + 32];
#pragma unroll
    for (int k = 0; k < HID; k++) {
        o0 += a[k] * sW2[k * OUTD + lane];
        o1 += a[k] * sW2[k * OUTD + lane + 32];
    }
    out[node * OUTD + lane]      = o0;
    out[node * OUTD + 32 + lane] = o1;
}

// ---------------- launch ----------------
extern "C" void kernel_launch(void* const* d_in, const int* in_sizes, int n_in,
                              void* d_out, int out_size) {
    const void*  E  = d_in[1];
    const float* X  = (const float*)d_in[2];
    const float* W1 = (const float*)d_in[3];
    const float* b1 = (const float*)d_in[4];
    const float* W2 = (const float*)d_in[5];
    const float* b2 = (const float*)d_in[6];
    float* out = (float*)d_out;

    int n  = in_sizes[0];
    int ne = in_sizes[1] / 2;

    k_init<<<(n + 255) / 256, 256>>>((const unsigned int*)E, n);
    k_edge_prep<<<(ne + 255) / 256, 256>>>(E, ne);

    int nblk = (n + 1023) / 1024;
    k_scan1<<<nblk, 256>>>(n);
    k_scan2<<<1, 128>>>(nblk, n);
    k_scan3<<<(n + 255) / 256, 256>>>(n);
    k_csr<<<(ne + 255) / 256, 256>>>(ne);

    k_gemm1<<<(n + G1_TR - 1) / G1_TR, 128>>>(X, W1, n);

    long long gth = (long long)n * 32;
    k_gather_h<<<(unsigned)((gth + 255) / 256), 256>>>(b1, n);
    k_gather_out<<<(unsigned)((gth + 255) / 256), 256>>>(W2, b2, out, n);
}

// round 3
// speedup vs baseline: 1.1432x; 1.1254x over previous
#include <cuda_runtime.h>

// Problem constants (fixed shapes for this problem instance)
#define NN     100000
#define NE     3200000
#define INDIM  512
#define HID    16
#define OUTD   64

// ---------------- device scratch (static, zero-initialized, no allocation) ----
__device__ __align__(16) int2  g_edge[NE];          // packed (src,dst)
__device__ __align__(16) int   g_srcs[NE];          // src grouped by dst (CSR adjacency)
__device__ __align__(16) int   g_deg[NN];           // self-resetting (zeroed by k_scan1)
__device__ __align__(16) float g_dinv[NN];
__device__ __align__(16) int   g_rowptr[NN + 1];
__device__ __align__(16) int   g_cursor[NN];
__device__ __align__(16) int   g_part[128];
__device__ __align__(16) float g_hn1[NN * HID];     // (X@W1) * dinv[row]
__device__ __align__(16) float g_hn2[NN * HID];     // relu(layer1 out) * dinv[row]

// ---------------- edge prep: decode edges (int64 or int32), count in-degree ----
// deg must be zero on entry: zero-initialized statically, and k_scan1 re-zeroes
// it every run, so each correctness run / graph replay starts from zero.
__global__ __launch_bounds__(256) void k_edge_prep(const void* __restrict__ E, int ne) {
    __shared__ int s_is64;
    int t = threadIdx.x;
    if (t < 32) {
        // int64 little-endian with values < 2^31 -> every odd 32-bit word is 0
        unsigned v = ((const unsigned int*)E)[2 * t + 1];
        unsigned any = __ballot_sync(0xffffffffu, v != 0u);
        if (t == 0) s_is64 = (any == 0u);
    }
    __syncthreads();
    int e0 = (blockIdx.x * 256 + t) * 2;
    if (e0 >= ne) return;
    int s0, d0, s1, d1;
    if (s_is64) {
        const longlong2* p = (const longlong2*)E;
        longlong2 ss = p[e0 >> 1];
        longlong2 dd = p[(ne + e0) >> 1];
        s0 = (int)ss.x; s1 = (int)ss.y; d0 = (int)dd.x; d1 = (int)dd.y;
    } else {
        const int2* p = (const int2*)E;
        int2 ss = p[e0 >> 1];
        int2 dd = p[(ne + e0) >> 1];
        s0 = ss.x; s1 = ss.y; d0 = dd.x; d1 = dd.y;
    }
    if (e0 + 1 < ne) {
        *(int4*)&g_edge[e0] = make_int4(s0, d0, s1, d1);
        atomicAdd(&g_deg[d0], 1);
        atomicAdd(&g_deg[d1], 1);
    } else {
        g_edge[e0] = make_int2(s0, d0);
        atomicAdd(&g_deg[d0], 1);
    }
}

// ---------------- scan pass 1: block-local exclusive scan of deg -> rowptr ----
// also: dinv = rsqrt(deg+1) (self loop), and resets deg to 0 for the next run.
__global__ __launch_bounds__(256) void k_scan1(int n) {
    __shared__ int ss[256];
    int t = threadIdx.x;
    int base = blockIdx.x * 1024 + t * 4;
    int v[4]; int s = 0;
#pragma unroll
    for (int m = 0; m < 4; m++) {
        int idx = base + m;
        int dg = 0;
        if (idx < n) {
            dg = g_deg[idx];
            g_deg[idx] = 0;                       // self-reset for next replay
            g_dinv[idx] = rsqrtf((float)(dg + 1)); // +1 self loop
        }
        v[m] = dg;
        s += v[m];
    }
    ss[t] = s;
    __syncthreads();
#pragma unroll
    for (int off = 1; off < 256; off <<= 1) {
        int tv = 0;
        if (t >= off) tv = ss[t - off];
        __syncthreads();
        ss[t] += tv;
        __syncthreads();
    }
    int run = ss[t] - s;   // exclusive within block
#pragma unroll
    for (int m = 0; m < 4; m++) {
        int idx = base + m;
        if (idx < n) g_rowptr[idx] = run;
        run += v[m];
    }
    if (t == 255) g_part[blockIdx.x] = ss[255];
}

// ---------------- scan pass 2+3 fused: every block redundantly scans the ------
// <=128 block partials in smem, then applies its block offset.
__global__ __launch_bounds__(256) void k_scan3(int n, int nblk) {
    __shared__ int sp[129];
    int t = threadIdx.x;
    if (t < 128) sp[t + 1] = (t < nblk) ? g_part[t] : 0;
    if (t == 0) sp[0] = 0;
    __syncthreads();
#pragma unroll
    for (int off = 1; off < 128; off <<= 1) {
        int add = 0;
        if (t < 128 && t >= off) add = sp[t - off + 1];
        __syncthreads();
        if (t < 128) sp[t + 1] += add;
        __syncthreads();
    }
    // sp[b] = exclusive prefix for block b; sp[nblk] = total edges
    int base = blockIdx.x * 1024 + t * 4;
    int boff = sp[base >> 10];
#pragma unroll
    for (int m = 0; m < 4; m++) {
        int idx = base + m;
        if (idx < n) {
            int val = g_rowptr[idx] + boff;
            g_rowptr[idx] = val;
            g_cursor[idx] = val;
        }
    }
    if (blockIdx.x == 0 && t == 0) g_rowptr[n] = sp[nblk];
}

// ---------------- counting-sort scatter: group edges by dst ----------------
__global__ __launch_bounds__(256) void k_csr(int ne) {
    int e0 = (blockIdx.x * blockDim.x + threadIdx.x) * 2;
    if (e0 >= ne) return;
    if (e0 + 1 < ne) {
        int4 v = *(const int4*)&g_edge[e0];
        int pos0 = atomicAdd(&g_cursor[v.y], 1);
        g_srcs[pos0] = v.x;
        int pos1 = atomicAdd(&g_cursor[v.w], 1);
        g_srcs[pos1] = v.z;
    } else {
        int2 v = g_edge[e0];
        int pos = atomicAdd(&g_cursor[v.y], 1);
        g_srcs[pos] = v.x;
    }
}

// ---------------- GEMM1: hn1 = (X @ W1) * dinv[row] ----------------
// 128 threads, block tile 256 rows x 16 cols; thread tile 8 rows x 4 cols.
// Shared traffic = 1.5B per lane-FMA -> FMA-pipe bound (not crossbar bound).
#define G1_TR 256
#define XSTR  20    // 16 + 4 pad words -> conflict-free row access
#define WSTRT 20

__global__ __launch_bounds__(128) void k_gemm1(const float* __restrict__ X,
                                               const float* __restrict__ W1, int n) {
    __shared__ __align__(16) float sX[G1_TR * XSTR];   // 20 KB
    __shared__ __align__(16) float sW[HID * WSTRT];    // 1.25 KB, restaged per kt
    int t  = threadIdx.x;
    int cg = t & 3;        // column group (4 cols)
    int rg = t >> 2;       // 0..31; thread rows = rg + 32*i

    float acc[8][4];
#pragma unroll
    for (int i = 0; i < 8; i++)
#pragma unroll
        for (int j = 0; j < 4; j++) acc[i][j] = 0.f;

    int row0 = blockIdx.x * G1_TR;
    const float4* X4 = (const float4*)X;

    for (int kt = 0; kt < INDIM / 16; kt++) {
        __syncthreads();
        // stage W tile (16 k x 16 j), transposed: sW[j][k']
#pragma unroll
        for (int r = 0; r < 2; r++) {
            int m = t + 128 * r;
            int kk = m >> 4, j = m & 15;
            sW[j * WSTRT + kk] = W1[(kt * 16 + kk) * 16 + j];
        }
        // stage X tile: 256 rows x 16 floats (8 float4 per thread)
#pragma unroll
        for (int mm = 0; mm < 8; mm++) {
            int r = rg + 32 * mm;
            int grow = row0 + r;
            float4 v = make_float4(0.f, 0.f, 0.f, 0.f);
            if (grow < n) v = X4[grow * (INDIM / 4) + kt * 4 + cg];
            *(float4*)&sX[r * XSTR + cg * 4] = v;
        }
        __syncthreads();
#pragma unroll
        for (int kk4 = 0; kk4 < 4; kk4++) {
            float4 wv[4];
#pragma unroll
            for (int j = 0; j < 4; j++)
                wv[j] = *(const float4*)&sW[(cg * 4 + j) * WSTRT + kk4 * 4];
#pragma unroll
            for (int i = 0; i < 8; i++) {
                float4 xv = *(const float4*)&sX[(rg + 32 * i) * XSTR + kk4 * 4];
#pragma unroll
                for (int j = 0; j < 4; j++)
                    acc[i][j] += xv.x * wv[j].x + xv.y * wv[j].y
                               + xv.z * wv[j].z + xv.w * wv[j].w;
            }
        }
    }

#pragma unroll
    for (int i = 0; i < 8; i++) {
        int row = row0 + rg + 32 * i;
        if (row < n) {
            float dv = g_dinv[row];
            float4 o = make_float4(acc[i][0] * dv, acc[i][1] * dv,
                                   acc[i][2] * dv, acc[i][3] * dv);
            *(float4*)&g_hn1[row * HID + cg * 4] = o;
        }
    }
}

// ---------------- gather layer 1 + relu + dinv-prescale (writes hn2) ----------
// hn2[d] = relu( dinv[d]*(sum hn1[src] + hn1[d]) + b1 ) * dinv[d]
__global__ __launch_bounds__(256) void k_gather_h(const float* __restrict__ b1, int n) {
    int gt   = blockIdx.x * blockDim.x + threadIdx.x;
    int node = gt >> 5;
    if (node >= n) return;
    int lane = threadIdx.x & 31;
    int comp = lane & 3;   // which float4 of the 16-float row
    int sub  = lane >> 2;  // 8 parallel edge slots

    const float4* hn4 = (const float4*)g_hn1;
    int start = g_rowptr[node];
    int end   = g_rowptr[node + 1];

    float4 acc = make_float4(0.f, 0.f, 0.f, 0.f);
    for (int p = start + sub; p < end; p += 8) {
        int s = __ldg(&g_srcs[p]);
        float4 v = __ldg(&hn4[s * 4 + comp]);
        acc.x += v.x; acc.y += v.y; acc.z += v.z; acc.w += v.w;
    }
    if (sub == 0) {                       // fold in self loop once
        float4 self = hn4[node * 4 + comp];
        acc.x += self.x; acc.y += self.y; acc.z += self.z; acc.w += self.w;
    }
#pragma unroll
    for (int off = 4; off < 32; off <<= 1) {
        acc.x += __shfl_xor_sync(0xffffffffu, acc.x, off);
        acc.y += __shfl_xor_sync(0xffffffffu, acc.y, off);
        acc.z += __shfl_xor_sync(0xffffffffu, acc.z, off);
        acc.w += __shfl_xor_sync(0xffffffffu, acc.w, off);
    }
    if (sub == 0) {
        float dv = g_dinv[node];
        float4 b = ((const float4*)b1)[comp];
        float4 o;
        o.x = fmaxf(acc.x * dv + b.x, 0.f) * dv;
        o.y = fmaxf(acc.y * dv + b.y, 0.f) * dv;
        o.z = fmaxf(acc.z * dv + b.z, 0.f) * dv;
        o.w = fmaxf(acc.w * dv + b.w, 0.f) * dv;
        ((float4*)g_hn2)[node * 4 + comp] = o;
    }
}

// ---------------- gather layer 2 fused with GEMM2 (writes final output) -------
// agg[d] = dinv[d]*(sum hn2[src] + hn2[d]);  out[d] = agg[d] @ W2 + b2
__global__ __launch_bounds__(256) void k_gather_out(const float* __restrict__ W2,
                                                    const float* __restrict__ b2,
                                                    float* __restrict__ out, int n) {
    __shared__ __align__(16) float sW2[HID * OUTD];
    __shared__ float sB2[OUTD];
    int t = threadIdx.x;
    for (int m = t; m < HID * OUTD; m += 256) sW2[m] = W2[m];
    if (t < OUTD) sB2[t] = b2[t];
    __syncthreads();

    int node = (blockIdx.x * 256 + t) >> 5;
    if (node >= n) return;
    int lane = t & 31;
    int comp = lane & 3;
    int sub  = lane >> 2;

    const float4* hn4 = (const float4*)g_hn2;
    int start = g_rowptr[node];
    int end   = g_rowptr[node + 1];

    float4 acc = make_float4(0.f, 0.f, 0.f, 0.f);
    for (int p = start + sub; p < end; p += 8) {
        int s = __ldg(&g_srcs[p]);
        float4 v = __ldg(&hn4[s * 4 + comp]);
        acc.x += v.x; acc.y += v.y; acc.z += v.z; acc.w += v.w;
    }
    if (sub == 0) {
        float4 self = hn4[node * 4 + comp];
        acc.x += self.x; acc.y += self.y; acc.z += self.z; acc.w += self.w;
    }
#pragma unroll
    for (int off = 4; off < 32; off <<= 1) {
        acc.x += __shfl_xor_sync(0xffffffffu, acc.x, off);
        acc.y += __shfl_xor_sync(0xffffffffu, acc.y, off);
        acc.z += __shfl_xor_sync(0xffffffffu, acc.z, off);
        acc.w += __shfl_xor_sync(0xffffffffu, acc.w, off);
    }
    float dv = g_dinv[node];
    acc.x *= dv; acc.y *= dv; acc.z *= dv; acc.w *= dv;

    // broadcast the 16 aggregated values to all lanes (lanes 0..3 hold comps 0..3)
    float a[HID];
#pragma unroll
    for (int c = 0; c < 4; c++) {
        a[4 * c + 0] = __shfl_sync(0xffffffffu, acc.x, c);
        a[4 * c + 1] = __shfl_sync(0xffffffffu, acc.y, c);
        a[4 * c + 2] = __shfl_sync(0xffffffffu, acc.z, c);
        a[4 * c + 3] = __shfl_sync(0xffffffffu, acc.w, c);
    }

    // each lane computes output columns lane and lane+32
    float o0 = sB2[lane];
    float o1 = sB2[lane + 32];
#pragma unroll
    for (int k = 0; k < HID; k++) {
        o0 += a[k] * sW2[k * OUTD + lane];
        o1 += a[k] * sW2[k * OUTD + lane + 32];
    }
    out[node * OUTD + lane]      = o0;
    out[node * OUTD + 32 + lane] = o1;
}

// ---------------- launch ----------------
extern "C" void kernel_launch(void* const* d_in, const int* in_sizes, int n_in,
                              void* d_out, int out_size) {
    const void*  E  = d_in[1];
    const float* X  = (const float*)d_in[2];
    const float* W1 = (const float*)d_in[3];
    const float* b1 = (const float*)d_in[4];
    const float* W2 = (const float*)d_in[5];
    const float* b2 = (const float*)d_in[6];
    float* out = (float*)d_out;

    int n  = in_sizes[0];
    int ne = in_sizes[1] / 2;

    int nblk = (n + 1023) / 1024;
    k_edge_prep<<<(ne / 2 + 255) / 256, 256>>>(E, ne);
    k_scan1<<<nblk, 256>>>(n);
    k_scan3<<<nblk, 256>>>(n, nblk);
    k_csr<<<(ne / 2 + 255) / 256, 256>>>(ne);

    k_gemm1<<<(n + G1_TR - 1) / G1_TR, 128>>>(X, W1, n);

    long long gth = (long long)n * 32;
    k_gather_h<<<(unsigned)((gth + 255) / 256), 256>>>(b1, n);
    k_gather_out<<<(unsigned)((gth + 255) / 256), 256>>>(W2, b2, out, n);
}

// round 4
// speedup vs baseline: 1.2915x; 1.1297x over previous
#include <cuda_runtime.h>

// Problem constants (fixed shapes for this problem instance)
#define NN     100000
#define NE     3200000
#define INDIM  512
#define HID    16
#define OUTD   64

// ---------------- device scratch (static, zero-initialized, no allocation) ----
__device__ __align__(16) int   g_srcs[NE];          // src grouped by dst (CSR adjacency)
__device__ __align__(16) int   g_deg[NN];           // self-resetting (zeroed by k_scan1)
__device__ __align__(16) float g_dinv[NN];
__device__ __align__(16) int   g_rowptr[NN + 1];
__device__ __align__(16) int   g_cursor[NN];
__device__ __align__(16) int   g_part[128];
__device__ __align__(16) float g_hn1[NN * HID];     // X@W1, then scaled by dinv[row]
__device__ __align__(16) float g_hn2[NN * HID];     // relu(layer1 out) * dinv[row]

// ---------------- edge prep: decode dst (int64 or int32), count in-degree ----
// deg must be zero on entry: zero-initialized statically, and k_scan1 re-zeroes
// it every run, so each correctness run / graph replay starts from zero.
__global__ __launch_bounds__(256) void k_edge_prep(const void* __restrict__ E, int ne) {
    __shared__ int s_is64;
    int t = threadIdx.x;
    if (t < 32) {
        // int64 little-endian with values < 2^31 -> every odd 32-bit word is 0
        unsigned v = ((const unsigned int*)E)[2 * t + 1];
        unsigned any = __ballot_sync(0xffffffffu, v != 0u);
        if (t == 0) s_is64 = (any == 0u);
    }
    __syncthreads();
    int e0 = (blockIdx.x * 256 + t) * 2;
    if (e0 >= ne) return;
    int d0, d1;
    if (s_is64) {
        const longlong2* p = (const longlong2*)E;
        longlong2 dd = p[(ne + e0) >> 1];
        d0 = (int)dd.x; d1 = (int)dd.y;
    } else {
        const int2* p = (const int2*)E;
        int2 dd = p[(ne + e0) >> 1];
        d0 = dd.x; d1 = dd.y;
    }
    atomicAdd(&g_deg[d0], 1);
    if (e0 + 1 < ne) atomicAdd(&g_deg[d1], 1);
}

// ---------------- scan pass 1: block-local exclusive scan of deg -> rowptr ----
// also: dinv = rsqrt(deg+1) (self loop), and resets deg to 0 for the next run.
__global__ __launch_bounds__(256) void k_scan1(int n) {
    __shared__ int ss[256];
    int t = threadIdx.x;
    int base = blockIdx.x * 1024 + t * 4;
    int v[4]; int s = 0;
#pragma unroll
    for (int m = 0; m < 4; m++) {
        int idx = base + m;
        int dg = 0;
        if (idx < n) {
            dg = g_deg[idx];
            g_deg[idx] = 0;                        // self-reset for next replay
            g_dinv[idx] = rsqrtf((float)(dg + 1)); // +1 self loop
        }
        v[m] = dg;
        s += v[m];
    }
    ss[t] = s;
    __syncthreads();
#pragma unroll
    for (int off = 1; off < 256; off <<= 1) {
        int tv = 0;
        if (t >= off) tv = ss[t - off];
        __syncthreads();
        ss[t] += tv;
        __syncthreads();
    }
    int run = ss[t] - s;   // exclusive within block
#pragma unroll
    for (int m = 0; m < 4; m++) {
        int idx = base + m;
        if (idx < n) g_rowptr[idx] = run;
        run += v[m];
    }
    if (t == 255) g_part[blockIdx.x] = ss[255];
}

// ---------------- scan pass 2+3 fused: every block redundantly scans the ------
// <=128 block partials in smem, then applies its block offset.
__global__ __launch_bounds__(256) void k_scan3(int n, int nblk) {
    __shared__ int sp[129];
    int t = threadIdx.x;
    if (t < 128) sp[t + 1] = (t < nblk) ? g_part[t] : 0;
    if (t == 0) sp[0] = 0;
    __syncthreads();
#pragma unroll
    for (int off = 1; off < 128; off <<= 1) {
        int add = 0;
        if (t < 128 && t >= off) add = sp[t - off + 1];
        __syncthreads();
        if (t < 128) sp[t + 1] += add;
        __syncthreads();
    }
    int base = blockIdx.x * 1024 + t * 4;
    int boff = sp[base >> 10];
#pragma unroll
    for (int m = 0; m < 4; m++) {
        int idx = base + m;
        if (idx < n) {
            int val = g_rowptr[idx] + boff;
            g_rowptr[idx] = val;
            g_cursor[idx] = val;
        }
    }
    if (blockIdx.x == 0 && t == 0) g_rowptr[n] = sp[nblk];
}

// ---------------- counting-sort scatter: group edges by dst (reads E direct) --
__global__ __launch_bounds__(256) void k_csr(const void* __restrict__ E, int ne) {
    __shared__ int s_is64;
    int t = threadIdx.x;
    if (t < 32) {
        unsigned v = ((const unsigned int*)E)[2 * t + 1];
        unsigned any = __ballot_sync(0xffffffffu, v != 0u);
        if (t == 0) s_is64 = (any == 0u);
    }
    __syncthreads();
    int e0 = (blockIdx.x * 256 + t) * 2;
    if (e0 >= ne) return;
    int s0, d0, s1, d1;
    if (s_is64) {
        const longlong2* p = (const longlong2*)E;
        longlong2 ss = p[e0 >> 1];
        longlong2 dd = p[(ne + e0) >> 1];
        s0 = (int)ss.x; s1 = (int)ss.y; d0 = (int)dd.x; d1 = (int)dd.y;
    } else {
        const int2* p = (const int2*)E;
        int2 ss = p[e0 >> 1];
        int2 dd = p[(ne + e0) >> 1];
        s0 = ss.x; s1 = ss.y; d0 = dd.x; d1 = dd.y;
    }
    int pos0 = atomicAdd(&g_cursor[d0], 1);
    g_srcs[pos0] = s0;
    if (e0 + 1 < ne) {
        int pos1 = atomicAdd(&g_cursor[d1], 1);
        g_srcs[pos1] = s1;
    }
}

// ---------------- GEMM1: g_hn1 = X @ W1 (raw, dinv applied by k_scale) --------
// 128 threads, block tile 256 rows x 16 cols; thread tile 8 rows x 4 cols.
#define G1_TR 256
#define XSTR  20    // 16 + 4 pad words -> conflict-free row access
#define WSTRT 20

__global__ __launch_bounds__(128) void k_gemm1(const float* __restrict__ X,
                                               const float* __restrict__ W1, int n) {
    __shared__ __align__(16) float sX[G1_TR * XSTR];   // 20 KB
    __shared__ __align__(16) float sW[HID * WSTRT];    // restaged per kt
    int t  = threadIdx.x;
    int cg = t & 3;        // column group (4 cols)
    int rg = t >> 2;       // 0..31; thread rows = rg + 32*i

    float acc[8][4];
#pragma unroll
    for (int i = 0; i < 8; i++)
#pragma unroll
        for (int j = 0; j < 4; j++) acc[i][j] = 0.f;

    int row0 = blockIdx.x * G1_TR;
    const float4* X4 = (const float4*)X;

    for (int kt = 0; kt < INDIM / 16; kt++) {
        __syncthreads();
#pragma unroll
        for (int r = 0; r < 2; r++) {
            int m = t + 128 * r;
            int kk = m >> 4, j = m & 15;
            sW[j * WSTRT + kk] = W1[(kt * 16 + kk) * 16 + j];
        }
#pragma unroll
        for (int mm = 0; mm < 8; mm++) {
            int r = rg + 32 * mm;
            int grow = row0 + r;
            float4 v = make_float4(0.f, 0.f, 0.f, 0.f);
            if (grow < n) v = X4[grow * (INDIM / 4) + kt * 4 + cg];
            *(float4*)&sX[r * XSTR + cg * 4] = v;
        }
        __syncthreads();
#pragma unroll
        for (int kk4 = 0; kk4 < 4; kk4++) {
            float4 wv[4];
#pragma unroll
            for (int j = 0; j < 4; j++)
                wv[j] = *(const float4*)&sW[(cg * 4 + j) * WSTRT + kk4 * 4];
#pragma unroll
            for (int i = 0; i < 8; i++) {
                float4 xv = *(const float4*)&sX[(rg + 32 * i) * XSTR + kk4 * 4];
#pragma unroll
                for (int j = 0; j < 4; j++)
                    acc[i][j] += xv.x * wv[j].x + xv.y * wv[j].y
                               + xv.z * wv[j].z + xv.w * wv[j].w;
            }
        }
    }

#pragma unroll
    for (int i = 0; i < 8; i++) {
        int row = row0 + rg + 32 * i;
        if (row < n) {
            float4 o = make_float4(acc[i][0], acc[i][1], acc[i][2], acc[i][3]);
            *(float4*)&g_hn1[row * HID + cg * 4] = o;
        }
    }
}

// ---------------- scale: hn1 *= dinv[row] (in place) ----------------
__global__ __launch_bounds__(256) void k_scale(int n) {
    int i = blockIdx.x * blockDim.x + threadIdx.x;   // one float4 per thread
    if (i >= n * 4) return;
    float dv = g_dinv[i >> 2];
    float4 v = ((const float4*)g_hn1)[i];
    v.x *= dv; v.y *= dv; v.z *= dv; v.w *= dv;
    ((float4*)g_hn1)[i] = v;
}

// ---------------- gather layer 1 + relu + dinv-prescale (writes hn2) ----------
// hn2[d] = relu( dinv[d]*(sum hn1[src] + hn1[d]) + b1 ) * dinv[d]
__global__ __launch_bounds__(256) void k_gather_h(const float* __restrict__ b1, int n) {
    int gt   = blockIdx.x * blockDim.x + threadIdx.x;
    int node = gt >> 5;
    if (node >= n) return;
    int lane = threadIdx.x & 31;
    int comp = lane & 3;   // which float4 of the 16-float row
    int sub  = lane >> 2;  // 8 parallel edge slots

    const float4* hn4 = (const float4*)g_hn1;
    int start = g_rowptr[node];
    int end   = g_rowptr[node + 1];

    float4 acc = make_float4(0.f, 0.f, 0.f, 0.f);
    for (int p = start + sub; p < end; p += 8) {
        int s = __ldg(&g_srcs[p]);
        float4 v = __ldg(&hn4[s * 4 + comp]);
        acc.x += v.x; acc.y += v.y; acc.z += v.z; acc.w += v.w;
    }
    if (sub == 0) {                       // fold in self loop once
        float4 self = hn4[node * 4 + comp];
        acc.x += self.x; acc.y += self.y; acc.z += self.z; acc.w += self.w;
    }
#pragma unroll
    for (int off = 4; off < 32; off <<= 1) {
        acc.x += __shfl_xor_sync(0xffffffffu, acc.x, off);
        acc.y += __shfl_xor_sync(0xffffffffu, acc.y, off);
        acc.z += __shfl_xor_sync(0xffffffffu, acc.z, off);
        acc.w += __shfl_xor_sync(0xffffffffu, acc.w, off);
    }
    if (sub == 0) {
        float dv = g_dinv[node];
        float4 b = ((const float4*)b1)[comp];
        float4 o;
        o.x = fmaxf(acc.x * dv + b.x, 0.f) * dv;
        o.y = fmaxf(acc.y * dv + b.y, 0.f) * dv;
        o.z = fmaxf(acc.z * dv + b.z, 0.f) * dv;
        o.w = fmaxf(acc.w * dv + b.w, 0.f) * dv;
        ((float4*)g_hn2)[node * 4 + comp] = o;
    }
}

// ---------------- gather layer 2 fused with GEMM2 (writes final output) -------
// agg[d] = dinv[d]*(sum hn2[src] + hn2[d]);  out[d] = agg[d] @ W2 + b2
__global__ __launch_bounds__(256) void k_gather_out(const float* __restrict__ W2,
                                                    const float* __restrict__ b2,
                                                    float* __restrict__ out, int n) {
    __shared__ __align__(16) float sW2[HID * OUTD];
    __shared__ float sB2[OUTD];
    int t = threadIdx.x;
    for (int m = t; m < HID * OUTD; m += 256) sW2[m] = W2[m];
    if (t < OUTD) sB2[t] = b2[t];
    __syncthreads();

    int node = (blockIdx.x * 256 + t) >> 5;
    if (node >= n) return;
    int lane = t & 31;
    int comp = lane & 3;
    int sub  = lane >> 2;

    const float4* hn4 = (const float4*)g_hn2;
    int start = g_rowptr[node];
    int end   = g_rowptr[node + 1];

    float4 acc = make_float4(0.f, 0.f, 0.f, 0.f);
    for (int p = start + sub; p < end; p += 8) {
        int s = __ldg(&g_srcs[p]);
        float4 v = __ldg(&hn4[s * 4 + comp]);
        acc.x += v.x; acc.y += v.y; acc.z += v.z; acc.w += v.w;
    }
    if (sub == 0) {
        float4 self = hn4[node * 4 + comp];
        acc.x += self.x; acc.y += self.y; acc.z += self.z; acc.w += self.w;
    }
#pragma unroll
    for (int off = 4; off < 32; off <<= 1) {
        acc.x += __shfl_xor_sync(0xffffffffu, acc.x, off);
        acc.y += __shfl_xor_sync(0xffffffffu, acc.y, off);
        acc.z += __shfl_xor_sync(0xffffffffu, acc.z, off);
        acc.w += __shfl_xor_sync(0xffffffffu, acc.w, off);
    }
    float dv = g_dinv[node];
    acc.x *= dv; acc.y *= dv; acc.z *= dv; acc.w *= dv;

    // broadcast the 16 aggregated values to all lanes (lanes 0..3 hold comps 0..3)
    float a[HID];
#pragma unroll
    for (int c = 0; c < 4; c++) {
        a[4 * c + 0] = __shfl_sync(0xffffffffu, acc.x, c);
        a[4 * c + 1] = __shfl_sync(0xffffffffu, acc.y, c);
        a[4 * c + 2] = __shfl_sync(0xffffffffu, acc.z, c);
        a[4 * c + 3] = __shfl_sync(0xffffffffu, acc.w, c);
    }

    float o0 = sB2[lane];
    float o1 = sB2[lane + 32];
#pragma unroll
    for (int k = 0; k < HID; k++) {
        o0 += a[k] * sW2[k * OUTD + lane];
        o1 += a[k] * sW2[k * OUTD + lane + 32];
    }
    out[node * OUTD + lane]      = o0;
    out[node * OUTD + 32 + lane] = o1;
}

// ---------------- launch (fork-join: GEMM1 overlaps the CSR build chain) ------
static cudaStream_t g_s2;
static cudaEvent_t  g_ev_fork, g_ev_dinv, g_ev_join;
static int          g_inited = 0;

extern "C" void kernel_launch(void* const* d_in, const int* in_sizes, int n_in,
                              void* d_out, int out_size) {
    const void*  E  = d_in[1];
    const float* X  = (const float*)d_in[2];
    const float* W1 = (const float*)d_in[3];
    const float* b1 = (const float*)d_in[4];
    const float* W2 = (const float*)d_in[5];
    const float* b2 = (const float*)d_in[6];
    float* out = (float*)d_out;

    int n  = in_sizes[0];
    int ne = in_sizes[1] / 2;

    if (!g_inited) {   // host-side infra only; per-call device work is identical
        cudaStreamCreateWithFlags(&g_s2, cudaStreamNonBlocking);
        cudaEventCreateWithFlags(&g_ev_fork, cudaEventDisableTiming);
        cudaEventCreateWithFlags(&g_ev_dinv, cudaEventDisableTiming);
        cudaEventCreateWithFlags(&g_ev_join, cudaEventDisableTiming);
        g_inited = 1;
    }

    int nblk = (n + 1023) / 1024;

    // fork: side stream runs GEMM1 (independent of edge chain)
    cudaEventRecord(g_ev_fork, 0);
    cudaStreamWaitEvent(g_s2, g_ev_fork, 0);
    k_gemm1<<<(n + G1_TR - 1) / G1_TR, 128, 0, g_s2>>>(X, W1, n);

    // main stream: edge histogram -> scan -> CSR scatter
    k_edge_prep<<<(ne / 2 + 255) / 256, 256>>>(E, ne);
    k_scan1<<<nblk, 256>>>(n);
    cudaEventRecord(g_ev_dinv, 0);                 // dinv ready
    k_scan3<<<nblk, 256>>>(n, nblk);
    k_csr<<<(ne / 2 + 255) / 256, 256>>>(E, ne);

    // side stream: scale hn1 by dinv once scan1 is done
    cudaStreamWaitEvent(g_s2, g_ev_dinv, 0);
    k_scale<<<(n * 4 + 255) / 256, 256, 0, g_s2>>>(n);
    cudaEventRecord(g_ev_join, g_s2);

    // join: gathers need both CSR (main) and scaled hn1 (side)
    cudaStreamWaitEvent(0, g_ev_join, 0);
    long long gth = (long long)n * 32;
    k_gather_h<<<(unsigned)((gth + 255) / 256), 256>>>(b1, n);
    k_gather_out<<<(unsigned)((gth + 255) / 256), 256>>>(W2, b2, out, n);
}

// round 6
// speedup vs baseline: 1.3142x; 1.0175x over previous
#include <cuda_runtime.h>
#include <cuda_fp16.h>

// Problem constants (fixed shapes for this problem instance)
#define NN     100000
#define NE     3200000
#define INDIM  512
#define HID    16
#define OUTD   64

// ---------------- device scratch (static, zero-initialized, no allocation) ----
__device__ __align__(16) int    g_srcs[NE];         // src grouped by dst (CSR adjacency)
__device__ __align__(16) int    g_deg[NN];          // self-resetting (zeroed by k_scan1)
__device__ __align__(16) float  g_dinv[NN];
__device__ __align__(16) int    g_rowptr[NN + 1];
__device__ __align__(16) int    g_cursor[NN];
__device__ __align__(16) int    g_part[128];
__device__ __align__(16) float  g_hn1[NN * HID];    // X@W1 (fp32, GEMM output)
__device__ __align__(16) __half g_hn1h[NN * HID];   // (X@W1)*dinv[row], fp16
__device__ __align__(16) __half g_hn2h[NN * HID];   // relu(layer1 out)*dinv[row], fp16

// ---------------- edge prep: decode dst (int64 or int32), count in-degree ----
// deg must be zero on entry: zero-initialized statically, and k_scan1 re-zeroes
// it every run, so each correctness run / graph replay starts from zero.
__global__ __launch_bounds__(256) void k_edge_prep(const void* __restrict__ E, int ne) {
    __shared__ int s_is64;
    int t = threadIdx.x;
    if (t < 32) {
        // int64 little-endian with values < 2^31 -> every odd 32-bit word is 0
        unsigned v = ((const unsigned int*)E)[2 * t + 1];
        unsigned any = __ballot_sync(0xffffffffu, v != 0u);
        if (t == 0) s_is64 = (any == 0u);
    }
    __syncthreads();
    int e0 = (blockIdx.x * 256 + t) * 2;
    if (e0 >= ne) return;
    int d0, d1;
    if (s_is64) {
        const longlong2* p = (const longlong2*)E;
        longlong2 dd = p[(ne + e0) >> 1];
        d0 = (int)dd.x; d1 = (int)dd.y;
    } else {
        const int2* p = (const int2*)E;
        int2 dd = p[(ne + e0) >> 1];
        d0 = dd.x; d1 = dd.y;
    }
    atomicAdd(&g_deg[d0], 1);
    if (e0 + 1 < ne) atomicAdd(&g_deg[d1], 1);
}

// ---------------- scan pass 1: block-local exclusive scan of deg -> rowptr ----
// also: dinv = rsqrt(deg+1) (self loop), and resets deg to 0 for the next run.
__global__ __launch_bounds__(256) void k_scan1(int n) {
    __shared__ int ss[256];
    int t = threadIdx.x;
    int base = blockIdx.x * 1024 + t * 4;
    int v[4]; int s = 0;
#pragma unroll
    for (int m = 0; m < 4; m++) {
        int idx = base + m;
        int dg = 0;
        if (idx < n) {
            dg = g_deg[idx];
            g_deg[idx] = 0;                        // self-reset for next replay
            g_dinv[idx] = rsqrtf((float)(dg + 1)); // +1 self loop
        }
        v[m] = dg;
        s += v[m];
    }
    ss[t] = s;
    __syncthreads();
#pragma unroll
    for (int off = 1; off < 256; off <<= 1) {
        int tv = 0;
        if (t >= off) tv = ss[t - off];
        __syncthreads();
        ss[t] += tv;
        __syncthreads();
    }
    int run = ss[t] - s;   // exclusive within block
#pragma unroll
    for (int m = 0; m < 4; m++) {
        int idx = base + m;
        if (idx < n) g_rowptr[idx] = run;
        run += v[m];
    }
    if (t == 255) g_part[blockIdx.x] = ss[255];
}

// ---------------- scan pass 2+3 fused: every block redundantly scans the ------
// <=128 block partials in smem, then applies its block offset.
__global__ __launch_bounds__(256) void k_scan3(int n, int nblk) {
    __shared__ int sp[129];
    int t = threadIdx.x;
    if (t < 128) sp[t + 1] = (t < nblk) ? g_part[t] : 0;
    if (t == 0) sp[0] = 0;
    __syncthreads();
#pragma unroll
    for (int off = 1; off < 128; off <<= 1) {
        int add = 0;
        if (t < 128 && t >= off) add = sp[t - off + 1];
        __syncthreads();
        if (t < 128) sp[t + 1] += add;
        __syncthreads();
    }
    int base = blockIdx.x * 1024 + t * 4;
    int boff = sp[base >> 10];
#pragma unroll
    for (int m = 0; m < 4; m++) {
        int idx = base + m;
        if (idx < n) {
            int val = g_rowptr[idx] + boff;
            g_rowptr[idx] = val;
            g_cursor[idx] = val;
        }
    }
    if (blockIdx.x == 0 && t == 0) g_rowptr[n] = sp[nblk];
}

// ---------------- counting-sort scatter: group edges by dst (reads E direct) --
__global__ __launch_bounds__(256) void k_csr(const void* __restrict__ E, int ne) {
    __shared__ int s_is64;
    int t = threadIdx.x;
    if (t < 32) {
        unsigned v = ((const unsigned int*)E)[2 * t + 1];
        unsigned any = __ballot_sync(0xffffffffu, v != 0u);
        if (t == 0) s_is64 = (any == 0u);
    }
    __syncthreads();
    int e0 = (blockIdx.x * 256 + t) * 2;
    if (e0 >= ne) return;
    int s0, d0, s1, d1;
    if (s_is64) {
        const longlong2* p = (const longlong2*)E;
        longlong2 ss = p[e0 >> 1];
        longlong2 dd = p[(ne + e0) >> 1];
        s0 = (int)ss.x; s1 = (int)ss.y; d0 = (int)dd.x; d1 = (int)dd.y;
    } else {
        const int2* p = (const int2*)E;
        int2 ss = p[e0 >> 1];
        int2 dd = p[(ne + e0) >> 1];
        s0 = ss.x; s1 = ss.y; d0 = dd.x; d1 = dd.y;
    }
    int pos0 = atomicAdd(&g_cursor[d0], 1);
    g_srcs[pos0] = s0;
    if (e0 + 1 < ne) {
        int pos1 = atomicAdd(&g_cursor[d1], 1);
        g_srcs[pos1] = s1;
    }
}

// ---------------- GEMM1: g_hn1 = X @ W1 (raw fp32) ----------------
// 128 threads, block tile 256 rows x 16 cols; thread tile 8 rows x 4 cols.
#define G1_TR 256
#define XSTR  20    // 16 + 4 pad words -> conflict-free row access
#define WSTRT 20

__global__ __launch_bounds__(128) void k_gemm1(const float* __restrict__ X,
                                               const float* __restrict__ W1, int n) {
    __shared__ __align__(16) float sX[G1_TR * XSTR];   // 20 KB
    __shared__ __align__(16) float sW[HID * WSTRT];
    int t  = threadIdx.x;
    int cg = t & 3;
    int rg = t >> 2;

    float acc[8][4];
#pragma unroll
    for (int i = 0; i < 8; i++)
#pragma unroll
        for (int j = 0; j < 4; j++) acc[i][j] = 0.f;

    int row0 = blockIdx.x * G1_TR;
    const float4* X4 = (const float4*)X;

    for (int kt = 0; kt < INDIM / 16; kt++) {
        __syncthreads();
#pragma unroll
        for (int r = 0; r < 2; r++) {
            int m = t + 128 * r;
            int kk = m >> 4, j = m & 15;
            sW[j * WSTRT + kk] = W1[(kt * 16 + kk) * 16 + j];
        }
#pragma unroll
        for (int mm = 0; mm < 8; mm++) {
            int r = rg + 32 * mm;
            int grow = row0 + r;
            float4 v = make_float4(0.f, 0.f, 0.f, 0.f);
            if (grow < n) v = X4[grow * (INDIM / 4) + kt * 4 + cg];
            *(float4*)&sX[r * XSTR + cg * 4] = v;
        }
        __syncthreads();
#pragma unroll
        for (int kk4 = 0; kk4 < 4; kk4++) {
            float4 wv[4];
#pragma unroll
            for (int j = 0; j < 4; j++)
                wv[j] = *(const float4*)&sW[(cg * 4 + j) * WSTRT + kk4 * 4];
#pragma unroll
            for (int i = 0; i < 8; i++) {
                float4 xv = *(const float4*)&sX[(rg + 32 * i) * XSTR + kk4 * 4];
#pragma unroll
                for (int j = 0; j < 4; j++)
                    acc[i][j] += xv.x * wv[j].x + xv.y * wv[j].y
                               + xv.z * wv[j].z + xv.w * wv[j].w;
            }
        }
    }

#pragma unroll
    for (int i = 0; i < 8; i++) {
        int row = row0 + rg + 32 * i;
        if (row < n) {
            float4 o = make_float4(acc[i][0], acc[i][1], acc[i][2], acc[i][3]);
            *(float4*)&g_hn1[row * HID + cg * 4] = o;
        }
    }
}

// ---------------- scale+convert: hn1h = fp16( hn1 * dinv[row] ) ----------------
__global__ __launch_bounds__(256) void k_scale(int n) {
    int i = blockIdx.x * blockDim.x + threadIdx.x;   // one float4 / half4 per thread
    if (i >= n * 4) return;
    float dv = g_dinv[i >> 2];
    float4 v = ((const float4*)g_hn1)[i];
    __half2 a = __floats2half2_rn(v.x * dv, v.y * dv);
    __half2 b = __floats2half2_rn(v.z * dv, v.w * dv);
    uint2 o = make_uint2(*(unsigned*)&a, *(unsigned*)&b);
    ((uint2*)g_hn1h)[i] = o;
}

// ---------------- gather layer 1 + relu + dinv-prescale (writes hn2h) ---------
// hn2[d] = relu( dinv[d]*(sum hn1h[src] + hn1h[d]) + b1 ) * dinv[d]
__global__ __launch_bounds__(256) void k_gather_h(const float* __restrict__ b1, int n) {
    int gt   = blockIdx.x * blockDim.x + threadIdx.x;
    int node = gt >> 5;
    if (node >= n) return;
    int lane = threadIdx.x & 31;
    int comp = lane & 3;   // which 4-dim chunk of the 16-dim row
    int sub  = lane >> 2;  // 8 parallel edge slots

    const uint2* hn = (const uint2*)g_hn1h;
    int start = g_rowptr[node];
    int end   = g_rowptr[node + 1];

    float4 acc = make_float4(0.f, 0.f, 0.f, 0.f);
    for (int p = start + sub; p < end; p += 8) {
        int s = __ldg(&g_srcs[p]);
        uint2 u = __ldg(&hn[s * 4 + comp]);
        float2 f0 = __half22float2(*(__half2*)&u.x);
        float2 f1 = __half22float2(*(__half2*)&u.y);
        acc.x += f0.x; acc.y += f0.y; acc.z += f1.x; acc.w += f1.y;
    }
    if (sub == 0) {                       // fold in self loop once
        uint2 u = hn[node * 4 + comp];
        float2 f0 = __half22float2(*(__half2*)&u.x);
        float2 f1 = __half22float2(*(__half2*)&u.y);
        acc.x += f0.x; acc.y += f0.y; acc.z += f1.x; acc.w += f1.y;
    }
#pragma unroll
    for (int off = 4; off < 32; off <<= 1) {
        acc.x += __shfl_xor_sync(0xffffffffu, acc.x, off);
        acc.y += __shfl_xor_sync(0xffffffffu, acc.y, off);
        acc.z += __shfl_xor_sync(0xffffffffu, acc.z, off);
        acc.w += __shfl_xor_sync(0xffffffffu, acc.w, off);
    }
    if (sub == 0) {
        float dv = g_dinv[node];
        float4 b = ((const float4*)b1)[comp];
        float4 o;
        o.x = fmaxf(acc.x * dv + b.x, 0.f) * dv;
        o.y = fmaxf(acc.y * dv + b.y, 0.f) * dv;
        o.z = fmaxf(acc.z * dv + b.z, 0.f) * dv;
        o.w = fmaxf(acc.w * dv + b.w, 0.f) * dv;
        __half2 ha = __floats2half2_rn(o.x, o.y);
        __half2 hb = __floats2half2_rn(o.z, o.w);
        ((uint2*)g_hn2h)[node * 4 + comp] =
            make_uint2(*(unsigned*)&ha, *(unsigned*)&hb);
    }
}

// ---------------- gather layer 2 fused with GEMM2 (writes final output) -------
// agg[d] = dinv[d]*(sum hn2h[src] + hn2h[d]);  out[d] = agg[d] @ W2 + b2
__global__ __launch_bounds__(256) void k_gather_out(const float* __restrict__ W2,
                                                    const float* __restrict__ b2,
                                                    float* __restrict__ out, int n) {
    __shared__ __align__(16) float sW2[HID * OUTD];
    __shared__ float sB2[OUTD];
    int t = threadIdx.x;
    for (int m = t; m < HID * OUTD; m += 256) sW2[m] = W2[m];
    if (t < OUTD) sB2[t] = b2[t];
    __syncthreads();

    int node = (blockIdx.x * 256 + t) >> 5;
    if (node >= n) return;
    int lane = t & 31;
    int comp = lane & 3;
    int sub  = lane >> 2;

    const uint2* hn = (const uint2*)g_hn2h;
    int start = g_rowptr[node];
    int end   = g_rowptr[node + 1];

    float4 acc = make_float4(0.f, 0.f, 0.f, 0.f);
    for (int p = start + sub; p < end; p += 8) {
        int s = __ldg(&g_srcs[p]);
        uint2 u = __ldg(&hn[s * 4 + comp]);
        float2 f0 = __half22float2(*(__half2*)&u.x);
        float2 f1 = __half22float2(*(__half2*)&u.y);
        acc.x += f0.x; acc.y += f0.y; acc.z += f1.x; acc.w += f1.y;
    }
    if (sub == 0) {
        uint2 u = hn[node * 4 + comp];
        float2 f0 = __half22float2(*(__half2*)&u.x);
        float2 f1 = __half22float2(*(__half2*)&u.y);
        acc.x += f0.x; acc.y += f0.y; acc.z += f1.x; acc.w += f1.y;
    }
#pragma unroll
    for (int off = 4; off < 32; off <<= 1) {
        acc.x += __shfl_xor_sync(0xffffffffu, acc.x, off);
        acc.y += __shfl_xor_sync(0xffffffffu, acc.y, off);
        acc.z += __shfl_xor_sync(0xffffffffu, acc.z, off);
        acc.w += __shfl_xor_sync(0xffffffffu, acc.w, off);
    }
    float dv = g_dinv[node];
    acc.x *= dv; acc.y *= dv; acc.z *= dv; acc.w *= dv;

    // broadcast the 16 aggregated values to all lanes (lanes 0..3 hold comps 0..3)
    float a[HID];
#pragma unroll
    for (int c = 0; c < 4; c++) {
        a[4 * c + 0] = __shfl_sync(0xffffffffu, acc.x, c);
        a[4 * c + 1] = __shfl_sync(0xffffffffu, acc.y, c);
        a[4 * c + 2] = __shfl_sync(0xffffffffu, acc.z, c);
        a[4 * c + 3] = __shfl_sync(0xffffffffu, acc.w, c);
    }

    float o0 = sB2[lane];
    float o1 = sB2[lane + 32];
#pragma unroll
    for (int k = 0; k < HID; k++) {
        o0 += a[k] * sW2[k * OUTD + lane];
        o1 += a[k] * sW2[k * OUTD + lane + 32];
    }
    out[node * OUTD + lane]      = o0;
    out[node * OUTD + 32 + lane] = o1;
}

// ---------------- launch (fork-join: GEMM1 overlaps the CSR build chain) ------
static cudaStream_t g_s2;
static cudaEvent_t  g_ev_fork, g_ev_dinv, g_ev_join;
static int          g_inited = 0;

extern "C" void kernel_launch(void* const* d_in, const int* in_sizes, int n_in,
                              void* d_out, int out_size) {
    const void*  E  = d_in[1];
    const float* X  = (const float*)d_in[2];
    const float* W1 = (const float*)d_in[3];
    const float* b1 = (const float*)d_in[4];
    const float* W2 = (const float*)d_in[5];
    const float* b2 = (const float*)d_in[6];
    float* out = (float*)d_out;

    int n  = in_sizes[0];
    int ne = in_sizes[1] / 2;

    if (!g_inited) {   // host-side infra only; per-call device work is identical
        cudaStreamCreateWithFlags(&g_s2, cudaStreamNonBlocking);
        cudaEventCreateWithFlags(&g_ev_fork, cudaEventDisableTiming);
        cudaEventCreateWithFlags(&g_ev_dinv, cudaEventDisableTiming);
        cudaEventCreateWithFlags(&g_ev_join, cudaEventDisableTiming);
        g_inited = 1;
    }

    int nblk = (n + 1023) / 1024;

    // fork: side stream runs GEMM1 (independent of edge chain)
    cudaEventRecord(g_ev_fork, 0);
    cudaStreamWaitEvent(g_s2, g_ev_fork, 0);
    k_gemm1<<<(n + G1_TR - 1) / G1_TR, 128, 0, g_s2>>>(X, W1, n);

    // main stream: edge histogram -> scan -> CSR scatter
    k_edge_prep<<<(ne / 2 + 255) / 256, 256>>>(E, ne);
    k_scan1<<<nblk, 256>>>(n);
    cudaEventRecord(g_ev_dinv, 0);                 // dinv ready
    k_scan3<<<nblk, 256>>>(n, nblk);
    k_csr<<<(ne / 2 + 255) / 256, 256>>>(E, ne);

    // side stream: scale hn1 by dinv and convert to fp16 once scan1 is done
    cudaStreamWaitEvent(g_s2, g_ev_dinv, 0);
    k_scale<<<(n * 4 + 255) / 256, 256, 0, g_s2>>>(n);
    cudaEventRecord(g_ev_join, g_s2);

    // join: gathers need both CSR (main) and scaled hn1h (side)
    cudaStreamWaitEvent(0, g_ev_join, 0);
    long long gth = (long long)n * 32;
    k_gather_h<<<(unsigned)((gth + 255) / 256), 256>>>(b1, n);
    k_gather_out<<<(unsigned)((gth + 255) / 256), 256>>>(W2, b2, out, n);
}